// round 1
// baseline (speedup 1.0000x reference)
#include <cuda_runtime.h>

#define Bn   16
#define Nn   16384
#define Sn   4096
#define Kn   16
#define FC   68      // fused channels: 64 points + 3 xyz + 1 pad
#define CIN  67
#define CMID 16
#define DOUT 128
#define AGGD 1072    // 67*16

// Scratch (no allocations allowed -> __device__ globals)
__device__ float g_fused[(size_t)Bn * Nn * FC];     // ~71 MB, point-major gather layout
__device__ float g_agg[(size_t)Bn * Sn * AGGD];     // ~281 MB, per-point aggregated features

// ---------------------------------------------------------------------------
// Kernel 0: build point-major fused feature array: g_fused[b][n][0:64]=points,
// [64:67]=xyz, [67]=0.  Coalesced read (n-contiguous) and coalesced write.
// ---------------------------------------------------------------------------
__global__ void k_fuse(const float* __restrict__ xyz, const float* __restrict__ points)
{
    __shared__ float t[32][69];
    int b = blockIdx.y, n0 = blockIdx.x * 32;
    for (int i = threadIdx.x; i < 68 * 32; i += 256) {
        int c = i >> 5, nn = i & 31;
        int n = n0 + nn;
        float v = 0.f;
        if (c < 64)      v = points[(b * 64 + c) * Nn + n];
        else if (c < 67) v = xyz[(b * 3 + (c - 64)) * Nn + n];
        t[nn][c] = v;
    }
    __syncthreads();
    float* dst = g_fused + ((size_t)b * Nn + n0) * FC;
    for (int i = threadIdx.x; i < 32 * 68; i += 256) {
        dst[i] = t[i / 68][i % 68];
    }
}

// ---------------------------------------------------------------------------
// LayerNorm (+ leaky 0.2) helper on a register array, params from smem.
// ---------------------------------------------------------------------------
template <int NCH>
__device__ __forceinline__ void ln_leaky(float* h, const float* gmm, const float* bt)
{
    const float inv = 1.f / (float)NCH;
    float m = 0.f;
#pragma unroll
    for (int j = 0; j < NCH; j++) m += h[j];
    m *= inv;
    float v = 0.f;
#pragma unroll
    for (int j = 0; j < NCH; j++) { float d = h[j] - m; v += d * d; }
    v *= inv;
    float r = rsqrtf(v + 1e-5f);
#pragma unroll
    for (int j = 0; j < NCH; j++) {
        float y = (h[j] - m) * r * gmm[j] + bt[j];
        h[j] = y > 0.f ? y : 0.2f * y;
    }
}

// ---------------------------------------------------------------------------
// Kernel 1: one CTA (128 threads) per query point (b,s).
//   - gather 16 neighbors x 68 floats (float4, contiguous) into smem
//   - 16 threads run the WeightNet MLP (3->8->8->16, LN+leaky each)
//   - all threads compute agg[c*16+m] = sum_k feat[c][k] * w[k][m]
// ---------------------------------------------------------------------------
__global__ __launch_bounds__(128)
void k_agg(const int* __restrict__ nn_idx, const float* __restrict__ new_xyz,
           const float* __restrict__ w0, const float* __restrict__ b0,
           const float* __restrict__ gm0, const float* __restrict__ be0,
           const float* __restrict__ w1, const float* __restrict__ b1,
           const float* __restrict__ gm1, const float* __restrict__ be1,
           const float* __restrict__ w2, const float* __restrict__ b2,
           const float* __restrict__ gm2, const float* __restrict__ be2)
{
    __shared__ float g[Kn][FC];
    __shared__ float wk[Kn][17];
    __shared__ int   idxs[Kn];
    __shared__ float nx[3];
    __shared__ float wp[312];
    // wp layout: w0@0(24) b0@24 g0@32 be0@40 w1@48(64) b1@112 g1@120 be1@128
    //            w2@136(128) b2@264 g2@280 be2@296

    int s = blockIdx.x, b = blockIdx.y;
    int tid = threadIdx.x;

    if (tid < Kn) idxs[tid] = nn_idx[(b * Sn + s) * Kn + tid];
    if (tid >= 64 && tid < 67) nx[tid - 64] = new_xyz[(b * 3 + (tid - 64)) * Sn + s];

    if (tid < 24) wp[tid] = w0[tid];
    if (tid < 8) {
        wp[24 + tid] = b0[tid];  wp[32 + tid] = gm0[tid]; wp[40 + tid] = be0[tid];
        wp[112 + tid] = b1[tid]; wp[120 + tid] = gm1[tid]; wp[128 + tid] = be1[tid];
    }
    if (tid < 64) wp[48 + tid] = w1[tid];
    wp[136 + tid] = w2[tid];                 // 128 elements, blockDim==128
    if (tid < 16) {
        wp[264 + tid] = b2[tid]; wp[280 + tid] = gm2[tid]; wp[296 + tid] = be2[tid];
    }
    __syncthreads();

    // Gather: 16 neighbors x 17 float4 (=68 floats each)
    for (int i = tid; i < Kn * (FC / 4); i += 128) {
        int k = i / 17, c = i - k * 17;
        const float4* src = (const float4*)(g_fused + ((size_t)b * Nn + idxs[k]) * FC);
        ((float4*)(&g[k][0]))[c] = src[c];
    }
    __syncthreads();

    if (tid < Kn) {
        int k = tid;
        float x0 = g[k][64] - nx[0], x1 = g[k][65] - nx[1], x2 = g[k][66] - nx[2];
        g[k][64] = x0; g[k][65] = x1; g[k][66] = x2;   // feat channels 64..66 = gxn

        float h[8];
#pragma unroll
        for (int j = 0; j < 8; j++)
            h[j] = x0 * wp[j] + x1 * wp[8 + j] + x2 * wp[16 + j] + wp[24 + j];
        ln_leaky<8>(h, wp + 32, wp + 40);

        float h2[8];
#pragma unroll
        for (int j = 0; j < 8; j++) {
            float a = wp[112 + j];
#pragma unroll
            for (int r = 0; r < 8; r++) a += h[r] * wp[48 + r * 8 + j];
            h2[j] = a;
        }
        ln_leaky<8>(h2, wp + 120, wp + 128);

        float h3[16];
#pragma unroll
        for (int j = 0; j < 16; j++) {
            float a = wp[264 + j];
#pragma unroll
            for (int r = 0; r < 8; r++) a += h2[r] * wp[136 + r * 16 + j];
            h3[j] = a;
        }
        ln_leaky<16>(h3, wp + 280, wp + 296);
#pragma unroll
        for (int j = 0; j < 16; j++) wk[k][j] = h3[j];
    }
    __syncthreads();

    float* outrow = g_agg + ((size_t)b * Sn + s) * AGGD;
    for (int i = tid; i < AGGD; i += 128) {
        int c = i >> 4, m = i & 15;
        float sum = 0.f;
#pragma unroll
        for (int k = 0; k < Kn; k++) sum += g[k][c] * wk[k][m];
        outrow[i] = sum;
    }
}

// ---------------------------------------------------------------------------
// Kernel 2: GEMM [65536,1072] x [1072,128] with fused bias + LayerNorm(128)
// + leaky, transposed coalesced store to out[B,128,S].
// Tile: 64 rows x 128 cols per CTA, 256 threads, KC=16 (67 chunks).
// warp w owns rows w*8..w*8+7, lane tx owns cols tx*4..tx*4+3.
// ---------------------------------------------------------------------------
__global__ __launch_bounds__(256)
void k_gemm(const float* __restrict__ wl, const float* __restrict__ bl,
            const float* __restrict__ gl, const float* __restrict__ bel,
            float* __restrict__ out)
{
    __shared__ float SM[128 * 65];       // 33.3 KB; union of (As 1024 + Bs 2048) and T
    float* As = SM;                      // [64][16]
    float* Bs = SM + 1024;               // [16][128]

    int tid = threadIdx.x;
    int w = tid >> 5, tx = tid & 31;
    int m0 = blockIdx.x * 64;

    float acc[8][4];
#pragma unroll
    for (int i = 0; i < 8; i++)
#pragma unroll
        for (int j = 0; j < 4; j++) acc[i][j] = 0.f;

    for (int kc = 0; kc < 67; kc++) {
        {   // A tile: 64 rows x 16 cols (one float4 per thread)
            int r = tid >> 2, q = tid & 3;
            float4 v = *(const float4*)(g_agg + (size_t)(m0 + r) * AGGD + kc * 16 + q * 4);
            *(float4*)(As + r * 16 + q * 4) = v;
        }
        {   // B tile: 16 rows x 128 cols (contiguous 2048 floats)
            const float4* src = (const float4*)(wl + kc * 16 * 128);
            ((float4*)Bs)[tid]       = src[tid];
            ((float4*)Bs)[tid + 256] = src[tid + 256];
        }
        __syncthreads();
#pragma unroll
        for (int kk = 0; kk < 16; kk++) {
            float4 bv = ((const float4*)(Bs + kk * 128))[tx];
#pragma unroll
            for (int i = 0; i < 8; i++) {
                float a = As[(w * 8 + i) * 16 + kk];
                acc[i][0] += a * bv.x; acc[i][1] += a * bv.y;
                acc[i][2] += a * bv.z; acc[i][3] += a * bv.w;
            }
        }
        __syncthreads();
    }

    int c0 = tx * 4;
    float blv[4], glv[4], bev[4];
#pragma unroll
    for (int j = 0; j < 4; j++) { blv[j] = bl[c0 + j]; glv[j] = gl[c0 + j]; bev[j] = bel[c0 + j]; }

    float* T = SM;                       // [128][65] transpose buffer (A/B smem dead now)
#pragma unroll
    for (int i = 0; i < 8; i++) {
        float vv[4];
#pragma unroll
        for (int j = 0; j < 4; j++) vv[j] = acc[i][j] + blv[j];
        float s1 = vv[0] + vv[1] + vv[2] + vv[3];
        float s2 = vv[0]*vv[0] + vv[1]*vv[1] + vv[2]*vv[2] + vv[3]*vv[3];
#pragma unroll
        for (int o = 16; o > 0; o >>= 1) {
            s1 += __shfl_xor_sync(0xffffffffu, s1, o);
            s2 += __shfl_xor_sync(0xffffffffu, s2, o);
        }
        float mean = s1 * (1.f / 128.f);
        float var  = s2 * (1.f / 128.f) - mean * mean;
        float rs   = rsqrtf(var + 1e-5f);
        int row = w * 8 + i;
#pragma unroll
        for (int j = 0; j < 4; j++) {
            float y = (vv[j] - mean) * rs * glv[j] + bev[j];
            y = y > 0.f ? y : 0.2f * y;
            T[(c0 + j) * 65 + row] = y;
        }
    }
    __syncthreads();

    int bb = m0 >> 12, s0 = m0 & 4095;   // 64-row tile never straddles a batch (4096%64==0)
    float* obase = out + (size_t)bb * 128 * Sn + s0;
    for (int i = tid; i < 8192; i += 256) {
        int d = i >> 6, rr = i & 63;
        obase[d * Sn + rr] = T[d * 65 + rr];
    }
}

// ---------------------------------------------------------------------------
extern "C" void kernel_launch(void* const* d_in, const int* in_sizes, int n_in,
                              void* d_out, int out_size)
{
    const float* xyz     = (const float*)d_in[0];
    const float* points  = (const float*)d_in[1];
    const float* new_xyz = (const float*)d_in[2];
    const int*   nn_idx  = (const int*)  d_in[3];
    const float* w0  = (const float*)d_in[4];
    const float* b0  = (const float*)d_in[5];
    const float* gm0 = (const float*)d_in[6];
    const float* be0 = (const float*)d_in[7];
    const float* w1  = (const float*)d_in[8];
    const float* b1  = (const float*)d_in[9];
    const float* gm1 = (const float*)d_in[10];
    const float* be1 = (const float*)d_in[11];
    const float* w2  = (const float*)d_in[12];
    const float* b2  = (const float*)d_in[13];
    const float* gm2 = (const float*)d_in[14];
    const float* be2 = (const float*)d_in[15];
    const float* wl  = (const float*)d_in[16];
    const float* bl  = (const float*)d_in[17];
    const float* gl  = (const float*)d_in[18];
    const float* bel = (const float*)d_in[19];
    float* out = (float*)d_out;

    dim3 gFuse(Nn / 32, Bn);
    k_fuse<<<gFuse, 256>>>(xyz, points);

    dim3 gAgg(Sn, Bn);
    k_agg<<<gAgg, 128>>>(nn_idx, new_xyz,
                         w0, b0, gm0, be0,
                         w1, b1, gm1, be1,
                         w2, b2, gm2, be2);

    k_gemm<<<(Bn * Sn) / 64, 256>>>(wl, bl, gl, bel, out);
}

// round 3
// speedup vs baseline: 1.2386x; 1.2386x over previous
#include <cuda_runtime.h>
#include <cuda_bf16.h>
#include <cstdint>

#define Bn   16
#define Nn   16384
#define Sn   4096
#define Kn   16
#define FC   68      // fused channels: 64 points + 3 xyz + 1 pad
#define CMID 16
#define DOUT 128
#define AGGD 1072    // 67*16
#define KPAD 1088

// Scratch (no allocations allowed -> __device__ globals)
__device__ float g_fused[(size_t)Bn * Nn * FC];          // ~71 MB
__device__ float g_agg[(size_t)Bn * Sn * AGGD];          // ~281 MB
__device__ __nv_bfloat16 g_Bhi[DOUT * KPAD];             // wl transposed [n][k], hi split
__device__ __nv_bfloat16 g_Blo[DOUT * KPAD];             // wl transposed [n][k], lo split

__device__ __forceinline__ uint32_t smem_u32(const void* p) {
    uint32_t a;
    asm("{ .reg .u64 t; cvta.to.shared.u64 t, %1; cvt.u32.u64 %0, t; }" : "=r"(a) : "l"(p));
    return a;
}

#define LDMX4(r0, r1, r2, r3, addr)                                            \
    asm volatile("ldmatrix.sync.aligned.m8n8.x4.shared.b16 {%0,%1,%2,%3}, [%4];" \
                 : "=r"(r0), "=r"(r1), "=r"(r2), "=r"(r3) : "r"(addr))

#define MMA16816(acc, a, b0, b1)                                               \
    asm volatile("mma.sync.aligned.m16n8k16.row.col.f32.bf16.bf16.f32 "        \
                 "{%0,%1,%2,%3},{%4,%5,%6,%7},{%8,%9},{%0,%1,%2,%3};"          \
                 : "+f"((acc)[0]), "+f"((acc)[1]), "+f"((acc)[2]), "+f"((acc)[3]) \
                 : "r"((a)[0]), "r"((a)[1]), "r"((a)[2]), "r"((a)[3]),         \
                   "r"(b0), "r"(b1))

// ===========================================================================
// Kernel 0: point-major fused feature array (unchanged)
// ===========================================================================
__global__ void k_fuse(const float* __restrict__ xyz, const float* __restrict__ points)
{
    __shared__ float t[32][69];
    int b = blockIdx.y, n0 = blockIdx.x * 32;
    for (int i = threadIdx.x; i < 68 * 32; i += 256) {
        int c = i >> 5, nn = i & 31;
        int n = n0 + nn;
        float v = 0.f;
        if (c < 64)      v = points[(b * 64 + c) * Nn + n];
        else if (c < 67) v = xyz[(b * 3 + (c - 64)) * Nn + n];
        t[nn][c] = v;
    }
    __syncthreads();
    float* dst = g_fused + ((size_t)b * Nn + n0) * FC;
    for (int i = threadIdx.x; i < 32 * 68; i += 256) {
        dst[i] = t[i / 68][i % 68];
    }
}

// ===========================================================================
// LayerNorm (+ leaky 0.2) helper (unchanged)
// ===========================================================================
template <int NCH>
__device__ __forceinline__ void ln_leaky(float* h, const float* gmm, const float* bt)
{
    const float inv = 1.f / (float)NCH;
    float m = 0.f;
#pragma unroll
    for (int j = 0; j < NCH; j++) m += h[j];
    m *= inv;
    float v = 0.f;
#pragma unroll
    for (int j = 0; j < NCH; j++) { float d = h[j] - m; v += d * d; }
    v *= inv;
    float r = rsqrtf(v + 1e-5f);
#pragma unroll
    for (int j = 0; j < NCH; j++) {
        float y = (h[j] - m) * r * gmm[j] + bt[j];
        h[j] = y > 0.f ? y : 0.2f * y;
    }
}

// ===========================================================================
// Kernel 1: per-point gather + WeightNet + 67x16 aggregation (unchanged)
// ===========================================================================
__global__ __launch_bounds__(128)
void k_agg(const int* __restrict__ nn_idx, const float* __restrict__ new_xyz,
           const float* __restrict__ w0, const float* __restrict__ b0,
           const float* __restrict__ gm0, const float* __restrict__ be0,
           const float* __restrict__ w1, const float* __restrict__ b1,
           const float* __restrict__ gm1, const float* __restrict__ be1,
           const float* __restrict__ w2, const float* __restrict__ b2,
           const float* __restrict__ gm2, const float* __restrict__ be2)
{
    __shared__ float g[Kn][FC];
    __shared__ float wk[Kn][17];
    __shared__ int   idxs[Kn];
    __shared__ float nx[3];
    __shared__ float wp[312];

    int s = blockIdx.x, b = blockIdx.y;
    int tid = threadIdx.x;

    if (tid < Kn) idxs[tid] = nn_idx[(b * Sn + s) * Kn + tid];
    if (tid >= 64 && tid < 67) nx[tid - 64] = new_xyz[(b * 3 + (tid - 64)) * Sn + s];

    if (tid < 24) wp[tid] = w0[tid];
    if (tid < 8) {
        wp[24 + tid] = b0[tid];  wp[32 + tid] = gm0[tid]; wp[40 + tid] = be0[tid];
        wp[112 + tid] = b1[tid]; wp[120 + tid] = gm1[tid]; wp[128 + tid] = be1[tid];
    }
    if (tid < 64) wp[48 + tid] = w1[tid];
    wp[136 + tid] = w2[tid];
    if (tid < 16) {
        wp[264 + tid] = b2[tid]; wp[280 + tid] = gm2[tid]; wp[296 + tid] = be2[tid];
    }
    __syncthreads();

    for (int i = tid; i < Kn * (FC / 4); i += 128) {
        int k = i / 17, c = i - k * 17;
        const float4* src = (const float4*)(g_fused + ((size_t)b * Nn + idxs[k]) * FC);
        ((float4*)(&g[k][0]))[c] = src[c];
    }
    __syncthreads();

    if (tid < Kn) {
        int k = tid;
        float x0 = g[k][64] - nx[0], x1 = g[k][65] - nx[1], x2 = g[k][66] - nx[2];
        g[k][64] = x0; g[k][65] = x1; g[k][66] = x2;

        float h[8];
#pragma unroll
        for (int j = 0; j < 8; j++)
            h[j] = x0 * wp[j] + x1 * wp[8 + j] + x2 * wp[16 + j] + wp[24 + j];
        ln_leaky<8>(h, wp + 32, wp + 40);

        float h2[8];
#pragma unroll
        for (int j = 0; j < 8; j++) {
            float a = wp[112 + j];
#pragma unroll
            for (int r = 0; r < 8; r++) a += h[r] * wp[48 + r * 8 + j];
            h2[j] = a;
        }
        ln_leaky<8>(h2, wp + 120, wp + 128);

        float h3[16];
#pragma unroll
        for (int j = 0; j < 16; j++) {
            float a = wp[264 + j];
#pragma unroll
            for (int r = 0; r < 8; r++) a += h2[r] * wp[136 + r * 16 + j];
            h3[j] = a;
        }
        ln_leaky<16>(h3, wp + 280, wp + 296);
#pragma unroll
        for (int j = 0; j < 16; j++) wk[k][j] = h3[j];
    }
    __syncthreads();

    float* outrow = g_agg + ((size_t)b * Sn + s) * AGGD;
    for (int i = tid; i < AGGD; i += 128) {
        int c = i >> 4, m = i & 15;
        float sum = 0.f;
#pragma unroll
        for (int k = 0; k < Kn; k++) sum += g[k][c] * wk[k][m];
        outrow[i] = sum;
    }
}

// ===========================================================================
// Kernel 1.5: transpose wl [1072][128] -> [128][1088], split bf16 hi/lo
// ===========================================================================
__global__ void k_prepB(const float* __restrict__ wl)
{
    int idx = blockIdx.x * 256 + threadIdx.x;
    if (idx >= DOUT * KPAD) return;
    int n = idx / KPAD, k = idx - n * KPAD;
    float v = (k < AGGD) ? wl[k * DOUT + n] : 0.f;
    __nv_bfloat16 h = __float2bfloat16(v);
    __nv_bfloat16 l = __float2bfloat16(v - __bfloat162float(h));
    g_Bhi[idx] = h;
    g_Blo[idx] = l;
}

// ===========================================================================
// Kernel 2: mma.sync bf16x3 GEMM  [65536,1072] x [1072,128] (+bias+LN+leaky)
//   CTA: 256 threads (8 warps), tile 64 x 128 ; warp = 16 x 64.
//   K: 67 chunks of 16. A split to bf16 hi/lo in-kernel; B pre-split.
// ===========================================================================
#define PITCH 24                 // bf16 elements per smem row (48 B)
#define AHI_OFF 0
#define ALO_OFF 3072
#define BHI_OFF 6144
#define BLO_OFF 12288
#define TPITCH  129

__global__ __launch_bounds__(256)
void k_gemm_mma(const float* __restrict__ bl, const float* __restrict__ gl,
                const float* __restrict__ bel, float* __restrict__ out)
{
    __shared__ float buf[64 * TPITCH];   // 33024 B: staging union epilogue T
    __shared__ float spb[DOUT], spg[DOUT], spe[DOUT];

    char* bb = (char*)buf;
    int tid = threadIdx.x;
    int wid = tid >> 5, lane = tid & 31;
    int wm = wid & 3, wn = wid >> 2;     // warp tile: rows wm*16, cols wn*64
    int m0 = blockIdx.x * 64;

    if (tid < DOUT) { spb[tid] = bl[tid]; spg[tid] = gl[tid]; spe[tid] = bel[tid]; }

    // ldmatrix per-lane byte offsets
    uint32_t sb = smem_u32(buf);
    uint32_t aOff = (((lane & 15) * PITCH + (lane >> 4) * 8) * 2);
    uint32_t aHiAddr = sb + AHI_OFF + wm * 16 * PITCH * 2 + aOff;
    uint32_t aLoAddr = sb + ALO_OFF + wm * 16 * PITCH * 2 + aOff;
    uint32_t bOff = ((((lane >> 4) * 8 + (lane & 7)) * PITCH + ((lane >> 3) & 1) * 8) * 2);
    uint32_t bHiBase = sb + BHI_OFF + wn * 64 * PITCH * 2 + bOff;
    uint32_t bLoBase = sb + BLO_OFF + wn * 64 * PITCH * 2 + bOff;

    // global pointers for staging
    int arow = tid >> 2, aq = tid & 3;               // A: row 0..63, quad 0..3
    const float* ag = g_agg + (size_t)(m0 + arow) * AGGD + aq * 4;
    int bn = tid >> 1, bh = tid & 1;                 // B: n 0..127, half 0..1
    const __nv_bfloat16* bgh = g_Bhi + bn * KPAD + bh * 8;
    const __nv_bfloat16* bgl = g_Blo + bn * KPAD + bh * 8;
    char* aDstHi = bb + AHI_OFF + arow * PITCH * 2 + aq * 8;
    char* aDstLo = bb + ALO_OFF + arow * PITCH * 2 + aq * 8;
    char* bDstHi = bb + BHI_OFF + bn * PITCH * 2 + bh * 16;
    char* bDstLo = bb + BLO_OFF + bn * PITCH * 2 + bh * 16;

    float acc[8][4];
#pragma unroll
    for (int j = 0; j < 8; j++)
#pragma unroll
        for (int q = 0; q < 4; q++) acc[j][q] = 0.f;

    for (int c = 0; c < 67; c++) {
        // ---- stage A (fp32 -> bf16 hi/lo) ----
        float4 av = *(const float4*)(ag + c * 16);
        float f[4] = {av.x, av.y, av.z, av.w};
        uint32_t hh[2], ll[2];
#pragma unroll
        for (int p = 0; p < 2; p++) {
            __nv_bfloat16 h0 = __float2bfloat16(f[2 * p]);
            __nv_bfloat16 h1 = __float2bfloat16(f[2 * p + 1]);
            __nv_bfloat16 l0 = __float2bfloat16(f[2 * p] - __bfloat162float(h0));
            __nv_bfloat16 l1 = __float2bfloat16(f[2 * p + 1] - __bfloat162float(h1));
            hh[p] = (uint32_t)*(unsigned short*)&h0 | ((uint32_t)*(unsigned short*)&h1 << 16);
            ll[p] = (uint32_t)*(unsigned short*)&l0 | ((uint32_t)*(unsigned short*)&l1 << 16);
        }
        *(uint2*)aDstHi = make_uint2(hh[0], hh[1]);
        *(uint2*)aDstLo = make_uint2(ll[0], ll[1]);
        // ---- stage B (pre-split bf16) ----
        *(uint4*)bDstHi = *(const uint4*)(bgh + c * 16);
        *(uint4*)bDstLo = *(const uint4*)(bgl + c * 16);
        __syncthreads();

        // ---- MMA ----
        uint32_t ahi[4], alo[4];
        LDMX4(ahi[0], ahi[1], ahi[2], ahi[3], aHiAddr);
        LDMX4(alo[0], alo[1], alo[2], alo[3], aLoAddr);
#pragma unroll
        for (int g = 0; g < 4; g++) {
            uint32_t bhr[4], blr[4];
            LDMX4(bhr[0], bhr[1], bhr[2], bhr[3], bHiBase + g * 16 * PITCH * 2);
            LDMX4(blr[0], blr[1], blr[2], blr[3], bLoBase + g * 16 * PITCH * 2);
            MMA16816(acc[2 * g],     ahi, bhr[0], bhr[1]);
            MMA16816(acc[2 * g + 1], ahi, bhr[2], bhr[3]);
            MMA16816(acc[2 * g],     ahi, blr[0], blr[1]);
            MMA16816(acc[2 * g + 1], ahi, blr[2], blr[3]);
            MMA16816(acc[2 * g],     alo, bhr[0], bhr[1]);
            MMA16816(acc[2 * g + 1], alo, bhr[2], bhr[3]);
        }
        __syncthreads();
    }

    // ---- epilogue: dump acc (+bias) to T[64][129] ----
    float* T = buf;
    int r0 = wm * 16 + (lane >> 2);
    int cb = wn * 64 + (lane & 3) * 2;
#pragma unroll
    for (int j = 0; j < 8; j++) {
        int d = cb + j * 8;
        T[r0 * TPITCH + d]           = acc[j][0] + spb[d];
        T[r0 * TPITCH + d + 1]       = acc[j][1] + spb[d + 1];
        T[(r0 + 8) * TPITCH + d]     = acc[j][2] + spb[d];
        T[(r0 + 8) * TPITCH + d + 1] = acc[j][3] + spb[d + 1];
    }
    __syncthreads();

    // ---- LayerNorm: 4 lanes per row (32 cols each) ----
    {
        int r = tid >> 2, q = tid & 3;
        float v[32];
        float s1 = 0.f, s2 = 0.f;
#pragma unroll
        for (int i = 0; i < 32; i++) {
            v[i] = T[r * TPITCH + q * 32 + i];
            s1 += v[i]; s2 += v[i] * v[i];
        }
        s1 += __shfl_xor_sync(0xffffffffu, s1, 1);
        s2 += __shfl_xor_sync(0xffffffffu, s2, 1);
        s1 += __shfl_xor_sync(0xffffffffu, s1, 2);
        s2 += __shfl_xor_sync(0xffffffffu, s2, 2);
        float mean = s1 * (1.f / 128.f);
        float var  = s2 * (1.f / 128.f) - mean * mean;
        float rs   = rsqrtf(var + 1e-5f);
#pragma unroll
        for (int i = 0; i < 32; i++) {
            int d = q * 32 + i;
            float y = (v[i] - mean) * rs * spg[d] + spe[d];
            T[r * TPITCH + d] = y > 0.f ? y : 0.2f * y;
        }
    }
    __syncthreads();

    // ---- coalesced transposed store ----
    int b = m0 >> 12, s0 = m0 & 4095;
    float* ob = out + (size_t)b * DOUT * Sn + s0;
    for (int i = tid; i < 64 * DOUT; i += 256) {
        int d = i >> 6, r = i & 63;
        ob[(size_t)d * Sn + r] = T[r * TPITCH + d];
    }
}

// ===========================================================================
extern "C" void kernel_launch(void* const* d_in, const int* in_sizes, int n_in,
                              void* d_out, int out_size)
{
    const float* xyz     = (const float*)d_in[0];
    const float* points  = (const float*)d_in[1];
    const float* new_xyz = (const float*)d_in[2];
    const int*   nn_idx  = (const int*)  d_in[3];
    const float* w0  = (const float*)d_in[4];
    const float* b0  = (const float*)d_in[5];
    const float* gm0 = (const float*)d_in[6];
    const float* be0 = (const float*)d_in[7];
    const float* w1  = (const float*)d_in[8];
    const float* b1  = (const float*)d_in[9];
    const float* gm1 = (const float*)d_in[10];
    const float* be1 = (const float*)d_in[11];
    const float* w2  = (const float*)d_in[12];
    const float* b2  = (const float*)d_in[13];
    const float* gm2 = (const float*)d_in[14];
    const float* be2 = (const float*)d_in[15];
    const float* wl  = (const float*)d_in[16];
    const float* bl  = (const float*)d_in[17];
    const float* gl  = (const float*)d_in[18];
    const float* bel = (const float*)d_in[19];
    float* out = (float*)d_out;

    dim3 gFuse(Nn / 32, Bn);
    k_fuse<<<gFuse, 256>>>(xyz, points);

    k_prepB<<<(DOUT * KPAD + 255) / 256, 256>>>(wl);

    dim3 gAgg(Sn, Bn);
    k_agg<<<gAgg, 128>>>(nn_idx, new_xyz,
                         w0, b0, gm0, be0,
                         w1, b1, gm1, be1,
                         w2, b2, gm2, be2);

    k_gemm_mma<<<(Bn * Sn) / 64, 256>>>(bl, gl, bel, out);
}

// round 4
// speedup vs baseline: 1.4462x; 1.1676x over previous
#include <cuda_runtime.h>
#include <cuda_bf16.h>
#include <cstdint>

#define Bn   16
#define Nn   16384
#define Sn   4096
#define Kn   16
#define FC   68      // fused channels: 64 points + 3 xyz + 1 pad
#define CMID 16
#define DOUT 128
#define AGGD 1072    // 67*16
#define KPAD 1088    // 34 * 32

// Scratch (no allocations allowed -> __device__ globals; zero-initialized)
__device__ float g_fused[(size_t)Bn * Nn * FC];              // ~71 MB
__device__ __nv_bfloat16 g_Ahi[(size_t)Bn * Sn * KPAD];      // agg hi split, 142 MB
__device__ __nv_bfloat16 g_Alo[(size_t)Bn * Sn * KPAD];      // agg lo split, 142 MB
__device__ __nv_bfloat16 g_Bhi[DOUT * KPAD];                 // wl^T hi split
__device__ __nv_bfloat16 g_Blo[DOUT * KPAD];                 // wl^T lo split

__device__ __forceinline__ uint32_t smem_u32(const void* p) {
    uint32_t a;
    asm("{ .reg .u64 t; cvta.to.shared.u64 t, %1; cvt.u32.u64 %0, t; }" : "=r"(a) : "l"(p));
    return a;
}

#define LDMX4(r0, r1, r2, r3, addr)                                            \
    asm volatile("ldmatrix.sync.aligned.m8n8.x4.shared.b16 {%0,%1,%2,%3}, [%4];" \
                 : "=r"(r0), "=r"(r1), "=r"(r2), "=r"(r3) : "r"(addr))

#define MMA16816(acc, a, b0, b1)                                               \
    asm volatile("mma.sync.aligned.m16n8k16.row.col.f32.bf16.bf16.f32 "        \
                 "{%0,%1,%2,%3},{%4,%5,%6,%7},{%8,%9},{%0,%1,%2,%3};"          \
                 : "+f"((acc)[0]), "+f"((acc)[1]), "+f"((acc)[2]), "+f"((acc)[3]) \
                 : "r"((a)[0]), "r"((a)[1]), "r"((a)[2]), "r"((a)[3]),         \
                   "r"(b0), "r"(b1))

#define CP16(dst, src)                                                         \
    asm volatile("cp.async.cg.shared.global [%0], [%1], 16;" :: "r"(dst), "l"(src))
#define CP_COMMIT() asm volatile("cp.async.commit_group;" ::: "memory")
#define CP_WAIT(n)  asm volatile("cp.async.wait_group %0;" :: "n"(n) : "memory")

// ===========================================================================
// Kernel 0: point-major fused feature array
// ===========================================================================
__global__ void k_fuse(const float* __restrict__ xyz, const float* __restrict__ points)
{
    __shared__ float t[32][69];
    int b = blockIdx.y, n0 = blockIdx.x * 32;
    for (int i = threadIdx.x; i < 68 * 32; i += 256) {
        int c = i >> 5, nn = i & 31;
        int n = n0 + nn;
        float v = 0.f;
        if (c < 64)      v = points[(b * 64 + c) * Nn + n];
        else if (c < 67) v = xyz[(b * 3 + (c - 64)) * Nn + n];
        t[nn][c] = v;
    }
    __syncthreads();
    float* dst = g_fused + ((size_t)b * Nn + n0) * FC;
    for (int i = threadIdx.x; i < 32 * 68; i += 256) {
        dst[i] = t[i / 68][i % 68];
    }
}

// ===========================================================================
// LayerNorm (+ leaky 0.2) helper
// ===========================================================================
template <int NCH>
__device__ __forceinline__ void ln_leaky(float* h, const float* gmm, const float* bt)
{
    const float inv = 1.f / (float)NCH;
    float m = 0.f;
#pragma unroll
    for (int j = 0; j < NCH; j++) m += h[j];
    m *= inv;
    float v = 0.f;
#pragma unroll
    for (int j = 0; j < NCH; j++) { float d = h[j] - m; v += d * d; }
    v *= inv;
    float r = rsqrtf(v + 1e-5f);
#pragma unroll
    for (int j = 0; j < NCH; j++) {
        float y = (h[j] - m) * r * gmm[j] + bt[j];
        h[j] = y > 0.f ? y : 0.2f * y;
    }
}

// ===========================================================================
// Kernel 1: gather + WeightNet + 67x16 aggregation; outputs bf16 hi/lo splits
// ===========================================================================
__global__ __launch_bounds__(128)
void k_agg(const int* __restrict__ nn_idx, const float* __restrict__ new_xyz,
           const float* __restrict__ w0, const float* __restrict__ b0,
           const float* __restrict__ gm0, const float* __restrict__ be0,
           const float* __restrict__ w1, const float* __restrict__ b1,
           const float* __restrict__ gm1, const float* __restrict__ be1,
           const float* __restrict__ w2, const float* __restrict__ b2,
           const float* __restrict__ gm2, const float* __restrict__ be2)
{
    __shared__ float g[Kn][FC];
    __shared__ float wk[Kn][17];
    __shared__ int   idxs[Kn];
    __shared__ float nx[3];
    __shared__ float wp[312];

    int s = blockIdx.x, b = blockIdx.y;
    int tid = threadIdx.x;

    if (tid < Kn) idxs[tid] = nn_idx[(b * Sn + s) * Kn + tid];
    if (tid >= 64 && tid < 67) nx[tid - 64] = new_xyz[(b * 3 + (tid - 64)) * Sn + s];

    if (tid < 24) wp[tid] = w0[tid];
    if (tid < 8) {
        wp[24 + tid] = b0[tid];  wp[32 + tid] = gm0[tid]; wp[40 + tid] = be0[tid];
        wp[112 + tid] = b1[tid]; wp[120 + tid] = gm1[tid]; wp[128 + tid] = be1[tid];
    }
    if (tid < 64) wp[48 + tid] = w1[tid];
    wp[136 + tid] = w2[tid];
    if (tid < 16) {
        wp[264 + tid] = b2[tid]; wp[280 + tid] = gm2[tid]; wp[296 + tid] = be2[tid];
    }
    __syncthreads();

    for (int i = tid; i < Kn * (FC / 4); i += 128) {
        int k = i / 17, c = i - k * 17;
        const float4* src = (const float4*)(g_fused + ((size_t)b * Nn + idxs[k]) * FC);
        ((float4*)(&g[k][0]))[c] = src[c];
    }
    __syncthreads();

    if (tid < Kn) {
        int k = tid;
        float x0 = g[k][64] - nx[0], x1 = g[k][65] - nx[1], x2 = g[k][66] - nx[2];
        g[k][64] = x0; g[k][65] = x1; g[k][66] = x2;

        float h[8];
#pragma unroll
        for (int j = 0; j < 8; j++)
            h[j] = x0 * wp[j] + x1 * wp[8 + j] + x2 * wp[16 + j] + wp[24 + j];
        ln_leaky<8>(h, wp + 32, wp + 40);

        float h2[8];
#pragma unroll
        for (int j = 0; j < 8; j++) {
            float a = wp[112 + j];
#pragma unroll
            for (int r = 0; r < 8; r++) a += h[r] * wp[48 + r * 8 + j];
            h2[j] = a;
        }
        ln_leaky<8>(h2, wp + 120, wp + 128);

        float h3[16];
#pragma unroll
        for (int j = 0; j < 16; j++) {
            float a = wp[264 + j];
#pragma unroll
            for (int r = 0; r < 8; r++) a += h2[r] * wp[136 + r * 16 + j];
            h3[j] = a;
        }
        ln_leaky<16>(h3, wp + 280, wp + 296);
#pragma unroll
        for (int j = 0; j < 16; j++) wk[k][j] = h3[j];
    }
    __syncthreads();

    uint32_t* hrow = (uint32_t*)(g_Ahi + ((size_t)b * Sn + s) * KPAD);
    uint32_t* lrow = (uint32_t*)(g_Alo + ((size_t)b * Sn + s) * KPAD);
    for (int ip = tid; ip < AGGD / 2; ip += 128) {
        int e = ip * 2, c = e >> 4, m = e & 15;
        float s0 = 0.f, s1 = 0.f;
#pragma unroll
        for (int k = 0; k < Kn; k++) {
            float fv = g[k][c];
            s0 += fv * wk[k][m];
            s1 += fv * wk[k][m + 1];
        }
        __nv_bfloat16 h0 = __float2bfloat16(s0);
        __nv_bfloat16 h1 = __float2bfloat16(s1);
        __nv_bfloat16 l0 = __float2bfloat16(s0 - __bfloat162float(h0));
        __nv_bfloat16 l1 = __float2bfloat16(s1 - __bfloat162float(h1));
        hrow[ip] = (uint32_t)*(unsigned short*)&h0 | ((uint32_t)*(unsigned short*)&h1 << 16);
        lrow[ip] = (uint32_t)*(unsigned short*)&l0 | ((uint32_t)*(unsigned short*)&l1 << 16);
    }
}

// ===========================================================================
// Kernel 1.5: transpose wl [1072][128] -> [128][1088], split bf16 hi/lo
// ===========================================================================
__global__ void k_prepB(const float* __restrict__ wl)
{
    int idx = blockIdx.x * 256 + threadIdx.x;
    if (idx >= DOUT * KPAD) return;
    int n = idx / KPAD, k = idx - n * KPAD;
    float v = (k < AGGD) ? wl[k * DOUT + n] : 0.f;
    __nv_bfloat16 h = __float2bfloat16(v);
    __nv_bfloat16 l = __float2bfloat16(v - __bfloat162float(h));
    g_Bhi[idx] = h;
    g_Blo[idx] = l;
}

// ===========================================================================
// Kernel 2: pipelined mma.sync bf16x3 GEMM [65536,1088]x[1088,128]
//   CTA 256 thr (8 warps: 2m x 4n, warp tile 32x32), CTA tile 64x128.
//   K: 34 chunks of 32 (2 k16 sub-tiles), cp.async double buffer.
//   Smem sub-tile: rows of 16 bf16 at 48B pitch (conflict-free ldmatrix).
// ===========================================================================
#define PITCHB   48          // bytes per smem row
#define A_SUB    3072        // 64 rows * 48B
#define B_SUB    6144        // 128 rows * 48B
#define B_BASE   12288       // 4 A sub-blocks
#define STAGEB   36864       // B_BASE + 4 * B_SUB
#define GEMM_SMEM (2 * STAGEB)
#define TPITCH   129

__global__ __launch_bounds__(256)
void k_gemm_mma(const float* __restrict__ bl, const float* __restrict__ gl,
                const float* __restrict__ bel, float* __restrict__ out)
{
    extern __shared__ char dsm[];
    __shared__ float spb[DOUT], spg[DOUT], spe[DOUT];

    int tid = threadIdx.x;
    int wid = tid >> 5, lane = tid & 31;
    int wm = wid & 1, wn = wid >> 1;       // warp tile rows wm*32, cols wn*32
    int m0 = blockIdx.x * 64;

    if (tid < DOUT) { spb[tid] = bl[tid]; spg[tid] = gl[tid]; spe[tid] = bel[tid]; }

    uint32_t sb = smem_u32(dsm);
    // ldmatrix per-lane byte offsets (proven layout from R3)
    uint32_t aOff = (uint32_t)((lane & 15) * PITCHB + (lane >> 4) * 16);
    uint32_t bOff = (uint32_t)(((lane >> 4) * 8 + (lane & 7)) * PITCHB + ((lane >> 3) & 1) * 16);

    float acc[2][4][4];
#pragma unroll
    for (int f = 0; f < 2; f++)
#pragma unroll
        for (int q = 0; q < 4; q++)
#pragma unroll
            for (int r = 0; r < 4; r++) acc[f][q][r] = 0.f;

    // ---- staging helper (as macro-ish lambda) ----
    auto stage_copy = [&](int s, int c) {
        uint32_t stu = sb + s * STAGEB;
#pragma unroll
        for (int t = tid; t < 512; t += 256) {          // A: hi/lo, 2 sub, 64 rows, 2 halves
            int p = t >> 8, rem = t & 255, j = rem >> 7, r2 = rem & 127;
            int r = r2 >> 1, h = r2 & 1;
            const __nv_bfloat16* gA = p ? g_Alo : g_Ahi;
            const __nv_bfloat16* src = gA + (size_t)(m0 + r) * KPAD + c * 32 + j * 16 + h * 8;
            CP16(stu + (p * 2 + j) * A_SUB + r * PITCHB + h * 16, (const void*)src);
        }
#pragma unroll
        for (int t = tid; t < 1024; t += 256) {         // B: hi/lo, 2 sub, 128 rows, 2 halves
            int p = t >> 9, rem = t & 511, j = rem >> 8, r2 = rem & 255;
            int n = r2 >> 1, h = r2 & 1;
            const __nv_bfloat16* gB = p ? g_Blo : g_Bhi;
            const __nv_bfloat16* src = gB + (size_t)n * KPAD + c * 32 + j * 16 + h * 8;
            CP16(stu + B_BASE + (p * 2 + j) * B_SUB + n * PITCHB + h * 16, (const void*)src);
        }
    };

    stage_copy(0, 0);
    CP_COMMIT();

    for (int c = 0; c < 34; c++) {
        if (c + 1 < 34) stage_copy((c + 1) & 1, c + 1);
        CP_COMMIT();
        if (c + 1 < 34) { CP_WAIT(1); } else { CP_WAIT(0); }
        __syncthreads();

        uint32_t stu = sb + (c & 1) * STAGEB;
#pragma unroll
        for (int j = 0; j < 2; j++) {
            uint32_t ahi[2][4], alo[2][4];
#pragma unroll
            for (int f = 0; f < 2; f++) {
                uint32_t ra = (uint32_t)((wm * 32 + f * 16) * PITCHB) + aOff;
                LDMX4(ahi[f][0], ahi[f][1], ahi[f][2], ahi[f][3], stu + j * A_SUB + ra);
                LDMX4(alo[f][0], alo[f][1], alo[f][2], alo[f][3], stu + (2 + j) * A_SUB + ra);
            }
#pragma unroll
            for (int g = 0; g < 2; g++) {
                uint32_t rb = (uint32_t)((wn * 32 + g * 16) * PITCHB) + bOff;
                uint32_t bh[4], blr[4];
                LDMX4(bh[0], bh[1], bh[2], bh[3], stu + B_BASE + j * B_SUB + rb);
                LDMX4(blr[0], blr[1], blr[2], blr[3], stu + B_BASE + (2 + j) * B_SUB + rb);
#pragma unroll
                for (int f = 0; f < 2; f++) {
                    MMA16816(acc[f][2 * g],     ahi[f], bh[0],  bh[1]);
                    MMA16816(acc[f][2 * g + 1], ahi[f], bh[2],  bh[3]);
                    MMA16816(acc[f][2 * g],     ahi[f], blr[0], blr[1]);
                    MMA16816(acc[f][2 * g + 1], ahi[f], blr[2], blr[3]);
                    MMA16816(acc[f][2 * g],     alo[f], bh[0],  bh[1]);
                    MMA16816(acc[f][2 * g + 1], alo[f], bh[2],  bh[3]);
                }
            }
        }
        __syncthreads();
    }

    // ---- epilogue: acc (+bias) -> T[64][129] ----
    float* T = (float*)dsm;
#pragma unroll
    for (int f = 0; f < 2; f++) {
        int r0 = wm * 32 + f * 16 + (lane >> 2);
#pragma unroll
        for (int q = 0; q < 4; q++) {
            int d = wn * 32 + q * 8 + (lane & 3) * 2;
            T[r0 * TPITCH + d]           = acc[f][q][0] + spb[d];
            T[r0 * TPITCH + d + 1]       = acc[f][q][1] + spb[d + 1];
            T[(r0 + 8) * TPITCH + d]     = acc[f][q][2] + spb[d];
            T[(r0 + 8) * TPITCH + d + 1] = acc[f][q][3] + spb[d + 1];
        }
    }
    __syncthreads();

    // ---- LayerNorm: 4 lanes per row (32 cols each) ----
    {
        int r = tid >> 2, q = tid & 3;
        float v[32];
        float s1 = 0.f, s2 = 0.f;
#pragma unroll
        for (int i = 0; i < 32; i++) {
            v[i] = T[r * TPITCH + q * 32 + i];
            s1 += v[i]; s2 += v[i] * v[i];
        }
        s1 += __shfl_xor_sync(0xffffffffu, s1, 1);
        s2 += __shfl_xor_sync(0xffffffffu, s2, 1);
        s1 += __shfl_xor_sync(0xffffffffu, s1, 2);
        s2 += __shfl_xor_sync(0xffffffffu, s2, 2);
        float mean = s1 * (1.f / 128.f);
        float var  = s2 * (1.f / 128.f) - mean * mean;
        float rs   = rsqrtf(var + 1e-5f);
#pragma unroll
        for (int i = 0; i < 32; i++) {
            int d = q * 32 + i;
            float y = (v[i] - mean) * rs * spg[d] + spe[d];
            T[r * TPITCH + d] = y > 0.f ? y : 0.2f * y;
        }
    }
    __syncthreads();

    // ---- coalesced transposed store ----
    int b = m0 >> 12, s0 = m0 & 4095;
    float* ob = out + (size_t)b * DOUT * Sn + s0;
    for (int i = tid; i < 64 * DOUT; i += 256) {
        int d = i >> 6, r = i & 63;
        ob[(size_t)d * Sn + r] = T[r * TPITCH + d];
    }
}

// ===========================================================================
extern "C" void kernel_launch(void* const* d_in, const int* in_sizes, int n_in,
                              void* d_out, int out_size)
{
    const float* xyz     = (const float*)d_in[0];
    const float* points  = (const float*)d_in[1];
    const float* new_xyz = (const float*)d_in[2];
    const int*   nn_idx  = (const int*)  d_in[3];
    const float* w0  = (const float*)d_in[4];
    const float* b0  = (const float*)d_in[5];
    const float* gm0 = (const float*)d_in[6];
    const float* be0 = (const float*)d_in[7];
    const float* w1  = (const float*)d_in[8];
    const float* b1  = (const float*)d_in[9];
    const float* gm1 = (const float*)d_in[10];
    const float* be1 = (const float*)d_in[11];
    const float* w2  = (const float*)d_in[12];
    const float* b2  = (const float*)d_in[13];
    const float* gm2 = (const float*)d_in[14];
    const float* be2 = (const float*)d_in[15];
    const float* wl  = (const float*)d_in[16];
    const float* bl  = (const float*)d_in[17];
    const float* gl  = (const float*)d_in[18];
    const float* bel = (const float*)d_in[19];
    float* out = (float*)d_out;

    static int inited = 0;
    if (!inited) {
        cudaFuncSetAttribute(k_gemm_mma, cudaFuncAttributeMaxDynamicSharedMemorySize,
                             GEMM_SMEM);
        inited = 1;
    }

    dim3 gFuse(Nn / 32, Bn);
    k_fuse<<<gFuse, 256>>>(xyz, points);

    k_prepB<<<(DOUT * KPAD + 255) / 256, 256>>>(wl);

    dim3 gAgg(Sn, Bn);
    k_agg<<<gAgg, 128>>>(nn_idx, new_xyz,
                         w0, b0, gm0, be0,
                         w1, b1, gm1, be1,
                         w2, b2, gm2, be2);

    k_gemm_mma<<<(Bn * Sn) / 64, 256, GEMM_SMEM>>>(bl, gl, bel, out);
}